// round 12
// baseline (speedup 1.0000x reference)
#include <cuda_runtime.h>
#include <cstdint>

#define MQ   32000
#define HN   32
#define CC   64
#define KK   15
#define COUTN 120

typedef unsigned long long ull;

// scratch
__device__ float  g_h[(size_t)MQ * CC];        // hidden layer, (M,64)
__device__ float4 g_pts4[MQ];                   // padded s_pts
__device__ ull    g_w2i[KK * 256];              // w2 interleaved for kp dots

// ---------------- f32x2 packed helpers (sm_103a) ----------------
__device__ __forceinline__ ull pack2(float a, float b) {
    ull r; asm("mov.b64 %0,{%1,%2};" : "=l"(r) : "f"(a), "f"(b)); return r;
}
__device__ __forceinline__ void unpack2(ull v, float& a, float& b) {
    asm("mov.b64 {%0,%1},%2;" : "=f"(a), "=f"(b) : "l"(v));
}
__device__ __forceinline__ ull fma2(ull a, ull b, ull c) {
    ull d; asm("fma.rn.f32x2 %0,%1,%2,%3;" : "=l"(d) : "l"(a), "l"(b), "l"(c)); return d;
}
__device__ __forceinline__ ull mul2(ull a, ull b) {
    ull d; asm("mul.rn.f32x2 %0,%1,%2;" : "=l"(d) : "l"(a), "l"(b)); return d;
}
__device__ __forceinline__ ull add2(ull a, ull b) {
    ull d; asm("add.rn.f32x2 %0,%1,%2;" : "=l"(d) : "l"(a), "l"(b)); return d;
}

// ---------------------------------------------------------------------------
// mlp_l1: h = leaky(X @ W1 + b1) only (layer 2 is computed sparsely in kp).
// smem bytes: Xtp 34304 + w1s 16384 + b1s 256 = 50944
// ---------------------------------------------------------------------------
#define XSTR 67
__global__ __launch_bounds__(256, 2) void mlp_l1_kernel(
    const float* __restrict__ X,
    const float* __restrict__ w1,
    const float* __restrict__ b1,
    const float* __restrict__ w2,
    const float* __restrict__ s_pts)
{
    extern __shared__ __align__(16) char smc[];
    ull*   Xtp = reinterpret_cast<ull*>(smc);                 // 4288 ull
    float* w1s = reinterpret_cast<float*>(smc + 34304);       // 4096 f
    float* b1s = reinterpret_cast<float*>(smc + 50688);       // 64 f

    const int tid  = threadIdx.x;
    const int cg   = tid & 15;
    const int rg   = tid >> 4;
    const int rg4  = rg * 4;
    const int base = blockIdx.x * 128;

    // side job 1: repack this block's 128 s_pts rows into g_pts4
    {
        float* tmp = reinterpret_cast<float*>(smc);
        for (int i = tid; i < 384; i += 256) tmp[i] = s_pts[base * 3 + i];
        __syncthreads();
        if (tid < 128) {
            float4 v;
            v.x = tmp[tid*3+0]; v.y = tmp[tid*3+1]; v.z = tmp[tid*3+2]; v.w = 0.f;
            g_pts4[base + tid] = v;
        }
        __syncthreads();
    }

    // side job 2: blocks 0..14 build g_w2i[k][t][lane] = (w2[j][o], w2[j+1][o])
    // with j = (lane&3)*16 + 2t, o = k*8 + (lane>>2)
    if (blockIdx.x < KK) {
        const int k = blockIdx.x;
        const int t = tid >> 5, l = tid & 31;
        const int j = (l & 3) * 16 + 2 * t;
        const int o = k * 8 + (l >> 2);
        g_w2i[k * 256 + t * 32 + l] = pack2(w2[j * 120 + o], w2[(j + 1) * 120 + o]);
    }

    // stage weights + X transposed row-pair packed
    for (int i = tid; i < 4096; i += 256) w1s[i] = w1[i];
    if (tid < 64) b1s[tid] = b1[tid];
#pragma unroll
    for (int i = 0; i < 4; i++) {
        const int idx = tid + 256 * i;
        const int c4 = idx & 15, rp = idx >> 4;
        const float4 a = *reinterpret_cast<const float4*>(X + (size_t)(base + 2*rp    ) * 64 + c4*4);
        const float4 b = *reinterpret_cast<const float4*>(X + (size_t)(base + 2*rp + 1) * 64 + c4*4);
        Xtp[(c4*4+0)*XSTR + rp] = pack2(a.x, b.x);
        Xtp[(c4*4+1)*XSTR + rp] = pack2(a.y, b.y);
        Xtp[(c4*4+2)*XSTR + rp] = pack2(a.z, b.z);
        Xtp[(c4*4+3)*XSTR + rp] = pack2(a.w, b.w);
    }
    __syncthreads();

    // layer 1: 8 rows x 4 cols per thread
    const int j0 = cg * 4;
    ull acc[4][4];
#pragma unroll
    for (int p = 0; p < 4; p++)
#pragma unroll
        for (int q = 0; q < 4; q++) acc[p][q] = 0ull;

#pragma unroll 4
    for (int c = 0; c < 64; c++) {
        ull xp[4];
#pragma unroll
        for (int p = 0; p < 4; p++) xp[p] = Xtp[c*XSTR + rg4 + p];
        const float4 wv = *reinterpret_cast<const float4*>(&w1s[c*64 + j0]);
        const ull wd0 = pack2(wv.x, wv.x), wd1 = pack2(wv.y, wv.y);
        const ull wd2 = pack2(wv.z, wv.z), wd3 = pack2(wv.w, wv.w);
#pragma unroll
        for (int p = 0; p < 4; p++) {
            acc[p][0] = fma2(xp[p], wd0, acc[p][0]);
            acc[p][1] = fma2(xp[p], wd1, acc[p][1]);
            acc[p][2] = fma2(xp[p], wd2, acc[p][2]);
            acc[p][3] = fma2(xp[p], wd3, acc[p][3]);
        }
    }

    // bias + leaky, store h rows to global
#pragma unroll
    for (int p = 0; p < 4; p++) {
        const int r0 = base + rg*8 + 2*p;
        float4 v0, v1;
        float* v0p = &v0.x; float* v1p = &v1.x;
#pragma unroll
        for (int q = 0; q < 4; q++) {
            float lo, hi; unpack2(acc[p][q], lo, hi);
            const float bq = b1s[j0 + q];
            lo += bq; hi += bq;
            v0p[q] = (lo >= 0.f) ? lo : 0.1f * lo;
            v1p[q] = (hi >= 0.f) ? hi : 0.1f * hi;
        }
        *reinterpret_cast<float4*>(g_h + (size_t)r0 * 64 + j0)       = v0;
        *reinterpret_cast<float4*>(g_h + (size_t)(r0 + 1) * 64 + j0) = v1;
    }
}

// ---------------------------------------------------------------------------
// kp_kernel v6: geometry (kernel points in REGISTERS, 64-reg budget) +
// sparse on-the-fly modulation DEDUPED by distinct k + x4-batched gather.
// ---------------------------------------------------------------------------
__global__ __launch_bounds__(256, 4) void kp_kernel(
    const float* __restrict__ q_pts,
    const float* __restrict__ s_feats,
    const int*   __restrict__ nidx,
    const float* __restrict__ kpts,
    const float* __restrict__ Wg,
    float* __restrict__ out)
{
    __shared__ __align__(16) float sW[15 * 72];       // padded stride 72
    __shared__ __align__(16) float sh[8][66];         // h row per warp
    __shared__ float smodv[8][15][8];                 // mod per kernel point per group
    __shared__ __align__(16) ull   sact[8][32];       // compacted (infl, (k<<26)|(ind<<6))

    const int tid  = threadIdx.x;
    const int wid  = tid >> 5;
    const int lane = tid & 31;
    const int m    = blockIdx.x * 8 + wid;
    const unsigned FULL = 0xffffffffu;

    for (int i = tid; i < 960; i += 256) sW[(i >> 6) * 72 + (i & 63)] = Wg[i];
    // stage h row (coalesced LDG.64 per lane)
    *reinterpret_cast<ull*>(&sh[wid][lane * 2]) =
        *reinterpret_cast<const ull*>(g_h + (size_t)m * 64 + lane * 2);

    // kernel points in registers (broadcast LDG, hoisted under 64-reg budget)
    float kpx[15], kpy[15], kpz[15];
#pragma unroll
    for (int k = 0; k < 15; k++) {
        kpx[k] = __ldg(&kpts[k*3+0]);
        kpy[k] = __ldg(&kpts[k*3+1]);
        kpz[k] = __ldg(&kpts[k*3+2]);
    }

    // geometry: one neighbor per lane
    const int ind = nidx[m * HN + lane];
    const float qx = __ldg(&q_pts[m*3+0]), qy = __ldg(&q_pts[m*3+1]), qz = __ldg(&q_pts[m*3+2]);
    float4 p = g_pts4[ind];
    const float nx = p.x - qx, ny = p.y - qy, nz = p.z - qz;
    float best = 3.4e38f; int bk = 0;
#pragma unroll
    for (int k = 0; k < 15; k++) {
        float dx = nx - kpx[k];
        float dy = ny - kpy[k];
        float dz = nz - kpz[k];
        float d2 = fmaf(dx, dx, fmaf(dy, dy, dz*dz));
        if (d2 < best) { best = d2; bk = k; }   // strict <: first-min like argmin
    }

    // compact active neighbors (infl > 0 <=> best < 1)
    const unsigned mask = __ballot_sync(FULL, best < 1.0f);
    const int n = __popc(mask);
    if (best < 1.0f) {
        const float infl = 1.0f - sqrtf(best);
        const unsigned pk = ((unsigned)bk << 26) | ((unsigned)ind << 6);
        const int pos = __popc(mask & ((1u << lane) - 1u));
        sact[wid][pos] = ((ull)__float_as_uint(infl) << 32) | pk;
    }
    // distinct active kernel points
    unsigned km = __reduce_or_sync(FULL, (best < 1.0f) ? (1u << bk) : 0u);
    __syncthreads();   // sW/sh ready (single barrier also covers sact within warp)

    // on-the-fly modulation, one dot per DISTINCT active k.
    // lane = (g8 = lane>>2, pq = lane&3): partial dot over h[16pq..16pq+16).
    const int pq = lane & 3;
    const int g8 = lane >> 2;
    const ull* hrow = reinterpret_cast<const ull*>(&sh[wid][pq * 16]);
    while (km) {
        const int k = __ffs(km) - 1;
        km &= km - 1;
        const ull* wbase = g_w2i + k * 256 + lane;
        ull part = 0ull;
#pragma unroll
        for (int t = 0; t < 8; t++)
            part = fma2(hrow[t], __ldg(&wbase[t * 32]), part);
        float lo, hi; unpack2(part, lo, hi);
        float d = lo + hi;
        d += __shfl_xor_sync(FULL, d, 1);
        d += __shfl_xor_sync(FULL, d, 2);
        smodv[wid][k][g8] = 1.f / (1.f + __expf(-d));
    }
    __syncwarp();

    // counted sparse accumulation, batched x4 (independent loads first)
    const int c2 = lane << 1;
    ull acc0 = 0ull, acc1 = 0ull;
    for (int j = 0; j < n; j += 4) {
        ull f[4], w[4]; float sc[4];
#pragma unroll
        for (int u = 0; u < 4; u++) {
            const bool     v   = (j + u) < n;
            const int      idx = v ? (j + u) : (n - 1);
            const ull      geo = sact[wid][idx];
            const unsigned pkh = (unsigned)geo;
            const int      k   = pkh >> 26;
            const int      row = pkh & 0x03FFFFFF;
            f[u]  = *reinterpret_cast<const ull*>(s_feats + row + c2);
            w[u]  = *reinterpret_cast<const ull*>(&sW[k * 72 + c2]);
            const float s = v ? __uint_as_float((unsigned)(geo >> 32)) : 0.0f;
            sc[u] = smodv[wid][k][g8] * s;
        }
#pragma unroll
        for (int u = 0; u < 4; u++) {
            const ull t = mul2(w[u], pack2(sc[u], sc[u]));
            if (u & 1) acc1 = fma2(f[u], t, acc1);
            else       acc0 = fma2(f[u], t, acc0);
        }
    }
    *reinterpret_cast<ull*>(out + (size_t)m * 64 + c2) = add2(acc0, acc1);
}

// ---------------------------------------------------------------------------
extern "C" void kernel_launch(void* const* d_in, const int* in_sizes, int n_in,
                              void* d_out, int out_size)
{
    const float* q_pts   = (const float*)d_in[0];
    const float* s_pts   = (const float*)d_in[1];
    const float* s_feats = (const float*)d_in[2];
    const int*   nidx    = (const int*)  d_in[3];
    const float* kpts    = (const float*)d_in[4];
    const float* W       = (const float*)d_in[5];
    const float* w1      = (const float*)d_in[6];
    const float* b1      = (const float*)d_in[7];
    const float* w2      = (const float*)d_in[8];
    float* out = (float*)d_out;

    const int smem = 50944;
    static bool init = false;
    if (!init) {
        cudaFuncSetAttribute(mlp_l1_kernel, cudaFuncAttributeMaxDynamicSharedMemorySize, smem);
        init = true;
    }

    mlp_l1_kernel<<<250, 256, smem>>>(s_feats, w1, b1, w2, s_pts);
    kp_kernel<<<MQ / 8, 256>>>(q_pts, s_feats, nidx, kpts, W, out);
}

// round 13
// speedup vs baseline: 1.1050x; 1.1050x over previous
#include <cuda_runtime.h>
#include <cstdint>

#define MQ   32000
#define HN   32
#define CC   64
#define KK   15
#define COUTN 120

typedef unsigned long long ull;

// scratch
__device__ float  g_h[(size_t)MQ * CC];        // hidden layer, (M,64)
__device__ float4 g_pts4[MQ];                   // padded s_pts
__device__ ull    g_w2i[KK * 256];              // w2 interleaved for kp dots

// ---------------- f32x2 packed helpers (sm_103a) ----------------
__device__ __forceinline__ ull pack2(float a, float b) {
    ull r; asm("mov.b64 %0,{%1,%2};" : "=l"(r) : "f"(a), "f"(b)); return r;
}
__device__ __forceinline__ void unpack2(ull v, float& a, float& b) {
    asm("mov.b64 {%0,%1},%2;" : "=f"(a), "=f"(b) : "l"(v));
}
__device__ __forceinline__ ull fma2(ull a, ull b, ull c) {
    ull d; asm("fma.rn.f32x2 %0,%1,%2,%3;" : "=l"(d) : "l"(a), "l"(b), "l"(c)); return d;
}
__device__ __forceinline__ ull mul2(ull a, ull b) {
    ull d; asm("mul.rn.f32x2 %0,%1,%2;" : "=l"(d) : "l"(a), "l"(b)); return d;
}
__device__ __forceinline__ ull add2(ull a, ull b) {
    ull d; asm("add.rn.f32x2 %0,%1,%2;" : "=l"(d) : "l"(a), "l"(b)); return d;
}

// ---------------------------------------------------------------------------
// mlp_l1: h = leaky(X @ W1 + b1) (unchanged, ~11us known-good).
// smem bytes: Xtp 34304 + w1s 16384 + b1s 256 = 50944
// ---------------------------------------------------------------------------
#define XSTR 67
__global__ __launch_bounds__(256, 2) void mlp_l1_kernel(
    const float* __restrict__ X,
    const float* __restrict__ w1,
    const float* __restrict__ b1,
    const float* __restrict__ w2,
    const float* __restrict__ s_pts)
{
    extern __shared__ __align__(16) char smc[];
    ull*   Xtp = reinterpret_cast<ull*>(smc);
    float* w1s = reinterpret_cast<float*>(smc + 34304);
    float* b1s = reinterpret_cast<float*>(smc + 50688);

    const int tid  = threadIdx.x;
    const int cg   = tid & 15;
    const int rg   = tid >> 4;
    const int rg4  = rg * 4;
    const int base = blockIdx.x * 128;

    {
        float* tmp = reinterpret_cast<float*>(smc);
        for (int i = tid; i < 384; i += 256) tmp[i] = s_pts[base * 3 + i];
        __syncthreads();
        if (tid < 128) {
            float4 v;
            v.x = tmp[tid*3+0]; v.y = tmp[tid*3+1]; v.z = tmp[tid*3+2]; v.w = 0.f;
            g_pts4[base + tid] = v;
        }
        __syncthreads();
    }

    if (blockIdx.x < KK) {
        const int k = blockIdx.x;
        const int t = tid >> 5, l = tid & 31;
        const int j = (l & 3) * 16 + 2 * t;
        const int o = k * 8 + (l >> 2);
        g_w2i[k * 256 + t * 32 + l] = pack2(w2[j * 120 + o], w2[(j + 1) * 120 + o]);
    }

    for (int i = tid; i < 4096; i += 256) w1s[i] = w1[i];
    if (tid < 64) b1s[tid] = b1[tid];
#pragma unroll
    for (int i = 0; i < 4; i++) {
        const int idx = tid + 256 * i;
        const int c4 = idx & 15, rp = idx >> 4;
        const float4 a = *reinterpret_cast<const float4*>(X + (size_t)(base + 2*rp    ) * 64 + c4*4);
        const float4 b = *reinterpret_cast<const float4*>(X + (size_t)(base + 2*rp + 1) * 64 + c4*4);
        Xtp[(c4*4+0)*XSTR + rp] = pack2(a.x, b.x);
        Xtp[(c4*4+1)*XSTR + rp] = pack2(a.y, b.y);
        Xtp[(c4*4+2)*XSTR + rp] = pack2(a.z, b.z);
        Xtp[(c4*4+3)*XSTR + rp] = pack2(a.w, b.w);
    }
    __syncthreads();

    const int j0 = cg * 4;
    ull acc[4][4];
#pragma unroll
    for (int p = 0; p < 4; p++)
#pragma unroll
        for (int q = 0; q < 4; q++) acc[p][q] = 0ull;

#pragma unroll 4
    for (int c = 0; c < 64; c++) {
        ull xp[4];
#pragma unroll
        for (int p = 0; p < 4; p++) xp[p] = Xtp[c*XSTR + rg4 + p];
        const float4 wv = *reinterpret_cast<const float4*>(&w1s[c*64 + j0]);
        const ull wd0 = pack2(wv.x, wv.x), wd1 = pack2(wv.y, wv.y);
        const ull wd2 = pack2(wv.z, wv.z), wd3 = pack2(wv.w, wv.w);
#pragma unroll
        for (int p = 0; p < 4; p++) {
            acc[p][0] = fma2(xp[p], wd0, acc[p][0]);
            acc[p][1] = fma2(xp[p], wd1, acc[p][1]);
            acc[p][2] = fma2(xp[p], wd2, acc[p][2]);
            acc[p][3] = fma2(xp[p], wd3, acc[p][3]);
        }
    }

#pragma unroll
    for (int p = 0; p < 4; p++) {
        const int r0 = base + rg*8 + 2*p;
        float4 v0, v1;
        float* v0p = &v0.x; float* v1p = &v1.x;
#pragma unroll
        for (int q = 0; q < 4; q++) {
            float lo, hi; unpack2(acc[p][q], lo, hi);
            const float bq = b1s[j0 + q];
            lo += bq; hi += bq;
            v0p[q] = (lo >= 0.f) ? lo : 0.1f * lo;
            v1p[q] = (hi >= 0.f) ? hi : 0.1f * hi;
        }
        *reinterpret_cast<float4*>(g_h + (size_t)r0 * 64 + j0)       = v0;
        *reinterpret_cast<float4*>(g_h + (size_t)(r0 + 1) * 64 + j0) = v1;
    }
}

// ---------------------------------------------------------------------------
// kp_kernel v7: TWO queries per warp (double dependency chains), skp in
// shared (R11-style), mod dots deduped per distinct k, joint gather loop.
// ---------------------------------------------------------------------------
__global__ __launch_bounds__(256, 4) void kp_kernel(
    const float* __restrict__ q_pts,
    const float* __restrict__ s_feats,
    const int*   __restrict__ nidx,
    const float* __restrict__ kpts,
    const float* __restrict__ Wg,
    float* __restrict__ out)
{
    __shared__ __align__(16) float sW[15 * 72];       // padded stride 72
    __shared__ __align__(16) float skp[48];
    __shared__ __align__(16) float sh[8][2][66];      // h rows, 2 queries/warp
    __shared__ float smodv[8][2][15][8];
    __shared__ __align__(16) ull   sact[8][2][32];

    const int tid  = threadIdx.x;
    const int wid  = tid >> 5;
    const int lane = tid & 31;
    const int m0   = blockIdx.x * 16 + wid * 2;
    const int m1   = m0 + 1;
    const unsigned FULL = 0xffffffffu;

    for (int i = tid; i < 960; i += 256) sW[(i >> 6) * 72 + (i & 63)] = Wg[i];
    if (tid < 45) skp[tid] = kpts[tid];
    // h rows for both queries
    *reinterpret_cast<ull*>(&sh[wid][0][lane * 2]) =
        *reinterpret_cast<const ull*>(g_h + (size_t)m0 * 64 + lane * 2);
    *reinterpret_cast<ull*>(&sh[wid][1][lane * 2]) =
        *reinterpret_cast<const ull*>(g_h + (size_t)m1 * 64 + lane * 2);
    if (lane < 2) sact[wid][lane][0] = 0ull;   // safe clamp target

    // geometry inputs (two independent chains)
    const int ind0 = nidx[m0 * HN + lane];
    const int ind1 = nidx[m1 * HN + lane];
    const float q0x = __ldg(&q_pts[m0*3+0]), q0y = __ldg(&q_pts[m0*3+1]), q0z = __ldg(&q_pts[m0*3+2]);
    const float q1x = __ldg(&q_pts[m1*3+0]), q1y = __ldg(&q_pts[m1*3+1]), q1z = __ldg(&q_pts[m1*3+2]);
    const float4 p0 = g_pts4[ind0];
    const float4 p1 = g_pts4[ind1];
    const float n0x = p0.x - q0x, n0y = p0.y - q0y, n0z = p0.z - q0z;
    const float n1x = p1.x - q1x, n1y = p1.y - q1y, n1z = p1.z - q1z;

    __syncthreads();   // skp/sW staged (sh is per-warp, covered too)

    float best0 = 3.4e38f, best1 = 3.4e38f; int bk0 = 0, bk1 = 0;
#pragma unroll
    for (int k = 0; k < 15; k++) {
        const float kx = skp[k*3+0], ky = skp[k*3+1], kz = skp[k*3+2];
        float dx0 = n0x - kx, dy0 = n0y - ky, dz0 = n0z - kz;
        float dx1 = n1x - kx, dy1 = n1y - ky, dz1 = n1z - kz;
        float d20 = fmaf(dx0, dx0, fmaf(dy0, dy0, dz0*dz0));
        float d21 = fmaf(dx1, dx1, fmaf(dy1, dy1, dz1*dz1));
        if (d20 < best0) { best0 = d20; bk0 = k; }   // strict <: first-min
        if (d21 < best1) { best1 = d21; bk1 = k; }
    }

    // compact active neighbors for both queries
    const unsigned mask0 = __ballot_sync(FULL, best0 < 1.0f);
    const unsigned mask1 = __ballot_sync(FULL, best1 < 1.0f);
    const int n0 = __popc(mask0), n1 = __popc(mask1);
    __syncwarp();   // order the pre-zero before compaction stores
    if (best0 < 1.0f) {
        const float infl = 1.0f - sqrtf(best0);
        const unsigned pk = ((unsigned)bk0 << 26) | ((unsigned)ind0 << 6);
        sact[wid][0][__popc(mask0 & ((1u << lane) - 1u))] =
            ((ull)__float_as_uint(infl) << 32) | pk;
    }
    if (best1 < 1.0f) {
        const float infl = 1.0f - sqrtf(best1);
        const unsigned pk = ((unsigned)bk1 << 26) | ((unsigned)ind1 << 6);
        sact[wid][1][__popc(mask1 & ((1u << lane) - 1u))] =
            ((ull)__float_as_uint(infl) << 32) | pk;
    }
    unsigned km0 = __reduce_or_sync(FULL, (best0 < 1.0f) ? (1u << bk0) : 0u);
    unsigned km1 = __reduce_or_sync(FULL, (best1 < 1.0f) ? (1u << bk1) : 0u);
    __syncwarp();

    // on-the-fly modulation, one dot per DISTINCT active k per query.
    const int pq = lane & 3;
    const int g8 = lane >> 2;
#pragma unroll
    for (int q = 0; q < 2; q++) {
        unsigned km = q ? km1 : km0;
        const ull* hrow = reinterpret_cast<const ull*>(&sh[wid][q][pq * 16]);
        while (km) {
            const int k = __ffs(km) - 1;
            km &= km - 1;
            const ull* wbase = g_w2i + k * 256 + lane;
            ull part = 0ull;
#pragma unroll
            for (int t = 0; t < 8; t++)
                part = fma2(hrow[t], __ldg(&wbase[t * 32]), part);
            float lo, hi; unpack2(part, lo, hi);
            float d = lo + hi;
            d += __shfl_xor_sync(FULL, d, 1);
            d += __shfl_xor_sync(FULL, d, 2);
            smodv[wid][q][k][g8] = 1.f / (1.f + __expf(-d));
        }
    }
    __syncwarp();

    // joint gather: 2 slots per query per iteration -> 4 independent loads
    const int c2 = lane << 1;
    ull a00 = 0ull, a01 = 0ull, a10 = 0ull, a11 = 0ull;
    const int nmax = (n0 > n1) ? n0 : n1;
    for (int j = 0; j < nmax; j += 2) {
        ull f[4], w[4]; float sc[4];
#pragma unroll
        for (int u = 0; u < 4; u++) {
            const int q  = u >> 1;
            const int jj = j + (u & 1);
            const int nq = q ? n1 : n0;
            const bool v = jj < nq;
            const int idx = v ? jj : 0;
            const ull geo = sact[wid][q][idx];
            const unsigned pkh = (unsigned)geo;
            const int k   = pkh >> 26;
            const int row = pkh & 0x03FFFFFF;
            f[u] = *reinterpret_cast<const ull*>(s_feats + row + c2);
            w[u] = *reinterpret_cast<const ull*>(&sW[k * 72 + c2]);
            sc[u] = v ? smodv[wid][q][k][g8] * __uint_as_float((unsigned)(geo >> 32))
                      : 0.0f;
        }
        a00 = fma2(f[0], mul2(w[0], pack2(sc[0], sc[0])), a00);
        a01 = fma2(f[1], mul2(w[1], pack2(sc[1], sc[1])), a01);
        a10 = fma2(f[2], mul2(w[2], pack2(sc[2], sc[2])), a10);
        a11 = fma2(f[3], mul2(w[3], pack2(sc[3], sc[3])), a11);
    }
    *reinterpret_cast<ull*>(out + (size_t)m0 * 64 + c2) = add2(a00, a01);
    *reinterpret_cast<ull*>(out + (size_t)m1 * 64 + c2) = add2(a10, a11);
}

// ---------------------------------------------------------------------------
extern "C" void kernel_launch(void* const* d_in, const int* in_sizes, int n_in,
                              void* d_out, int out_size)
{
    const float* q_pts   = (const float*)d_in[0];
    const float* s_pts   = (const float*)d_in[1];
    const float* s_feats = (const float*)d_in[2];
    const int*   nidx    = (const int*)  d_in[3];
    const float* kpts    = (const float*)d_in[4];
    const float* W       = (const float*)d_in[5];
    const float* w1      = (const float*)d_in[6];
    const float* b1      = (const float*)d_in[7];
    const float* w2      = (const float*)d_in[8];
    float* out = (float*)d_out;

    const int smem = 50944;
    static bool init = false;
    if (!init) {
        cudaFuncSetAttribute(mlp_l1_kernel, cudaFuncAttributeMaxDynamicSharedMemorySize, smem);
        init = true;
    }

    mlp_l1_kernel<<<250, 256, smem>>>(s_feats, w1, b1, w2, s_pts);
    kp_kernel<<<MQ / 16, 256>>>(q_pts, s_feats, nidx, kpts, W, out);
}